// round 1
// baseline (speedup 1.0000x reference)
#include <cuda_runtime.h>
#include <math.h>

#define BB 4
#define NNODE 256
#define DIM 512
#define NH 8
#define KSP 25

// ---------------------------------------------------------------------------
// Scratch (no allocations allowed anywhere)
// ---------------------------------------------------------------------------
__device__ float g_cur [BB*NNODE*DIM];
__device__ float g_qkv [BB*NNODE*3*DIM];
__device__ float g_atto[BB*NNODE*DIM];
__device__ float g_lvl0[BB*NNODE*DIM];
__device__ float g_lvl1[BB*(NNODE/2)*DIM];
__device__ float g_lvl2[BB*(NNODE/4)*DIM];
__device__ float g_t1  [BB*NNODE*(DIM/2)];
__device__ float g_p   [BB*NNODE*DIM];
__device__ float g_cat [BB*NNODE*3*DIM];
__device__ float g_hier[BB*NNODE*DIM];
__device__ float g_hi  [BB*NNODE*DIM];
__device__ float g_hj  [BB*NNODE*DIM];
__device__ float g_sc  [BB*NNODE*NNODE];

// ---------------------------------------------------------------------------
// Generic SGEMM: C[M,Nc] = A[M,K] @ W[K,Nc] (+bias) (+relu)
// M, Nc multiples of 64; K multiple of 16. Block 256 thr, 64x64 tile, 4x4/thread.
// ---------------------------------------------------------------------------
__global__ void sgemm_k(const float* __restrict__ A, const float* __restrict__ W,
                        const float* __restrict__ bias, float* __restrict__ C,
                        int M, int K, int Nc, int relu)
{
    __shared__ float As[64][17];
    __shared__ float Ws[16][64];
    const int bm = blockIdx.y * 64, bn = blockIdx.x * 64;
    const int tid = threadIdx.x;
    const int tx = tid & 15, ty = tid >> 4;

    float acc[4][4];
#pragma unroll
    for (int i = 0; i < 4; i++)
#pragma unroll
        for (int j = 0; j < 4; j++) acc[i][j] = 0.f;

    for (int k0 = 0; k0 < K; k0 += 16) {
#pragma unroll
        for (int e = 0; e < 4; e++) {
            int idx = e * 256 + tid;
            int m  = idx >> 4, kk = idx & 15;
            As[m][kk] = A[(size_t)(bm + m) * K + k0 + kk];
            int kw = idx >> 6, nw = idx & 63;
            Ws[kw][nw] = W[(size_t)(k0 + kw) * Nc + bn + nw];
        }
        __syncthreads();
#pragma unroll
        for (int kk = 0; kk < 16; kk++) {
            float4 w4 = *(const float4*)&Ws[kk][tx * 4];
            float a0 = As[ty * 4 + 0][kk];
            float a1 = As[ty * 4 + 1][kk];
            float a2 = As[ty * 4 + 2][kk];
            float a3 = As[ty * 4 + 3][kk];
            acc[0][0] += a0 * w4.x; acc[0][1] += a0 * w4.y; acc[0][2] += a0 * w4.z; acc[0][3] += a0 * w4.w;
            acc[1][0] += a1 * w4.x; acc[1][1] += a1 * w4.y; acc[1][2] += a1 * w4.z; acc[1][3] += a1 * w4.w;
            acc[2][0] += a2 * w4.x; acc[2][1] += a2 * w4.y; acc[2][2] += a2 * w4.z; acc[2][3] += a2 * w4.w;
            acc[3][0] += a3 * w4.x; acc[3][1] += a3 * w4.y; acc[3][2] += a3 * w4.z; acc[3][3] += a3 * w4.w;
        }
        __syncthreads();
    }

    float4 bb = make_float4(0.f, 0.f, 0.f, 0.f);
    if (bias) bb = *(const float4*)&bias[bn + tx * 4];
#pragma unroll
    for (int i = 0; i < 4; i++) {
        int m = bm + ty * 4 + i;
        float4 r;
        r.x = acc[i][0] + bb.x;
        r.y = acc[i][1] + bb.y;
        r.z = acc[i][2] + bb.z;
        r.w = acc[i][3] + bb.w;
        if (relu) {
            r.x = fmaxf(r.x, 0.f); r.y = fmaxf(r.y, 0.f);
            r.z = fmaxf(r.z, 0.f); r.w = fmaxf(r.w, 0.f);
        }
        *(float4*)&C[(size_t)m * Nc + bn + tx * 4] = r;
    }
}

// ---------------------------------------------------------------------------
// Multi-head attention core: qkv [B, Nl, 3*DIM] -> out [B, Nl, DIM]
// grid (B*NH, qsplit), block 256. K/V resident in padded shared.
// ---------------------------------------------------------------------------
__global__ void attn_k(const float* __restrict__ qkv, float* __restrict__ out, int Nl)
{
    extern __shared__ float sm[];
    float* Ks = sm;                 // Nl*65
    float* Vs = Ks + Nl * 65;       // Nl*65
    float* qs = Vs + Nl * 65;       // 8*64
    float* ps = qs + 8 * 64;        // 8*Nl

    const int b = blockIdx.x >> 3, h = blockIdx.x & 7;
    const float* base = qkv + (size_t)b * Nl * (3 * DIM);
    const int tid = threadIdx.x, warp = tid >> 5, lane = tid & 31;

    for (int idx = tid; idx < Nl * 64; idx += 256) {
        int n = idx >> 6, d = idx & 63;
        Ks[n * 65 + d] = base[(size_t)n * (3 * DIM) + DIM     + h * 64 + d];
        Vs[n * 65 + d] = base[(size_t)n * (3 * DIM) + 2 * DIM + h * 64 + d];
    }
    __syncthreads();

    const int jcnt = Nl >> 5;   // <= 8
    for (int r = blockIdx.y * 8 + warp; r < Nl; r += 8 * gridDim.y) {
        qs[warp * 64 + lane]      = base[(size_t)r * (3 * DIM) + h * 64 + lane];
        qs[warp * 64 + 32 + lane] = base[(size_t)r * (3 * DIM) + h * 64 + 32 + lane];
        __syncwarp();

        float sv[8];
        float mx = -1e30f;
        for (int t = 0; t < jcnt; t++) {
            int j = t * 32 + lane;
            float s = 0.f;
#pragma unroll
            for (int d = 0; d < 64; d++) s += qs[warp * 64 + d] * Ks[j * 65 + d];
            s *= 0.125f;           // HD^-0.5
            sv[t] = s;
            mx = fmaxf(mx, s);
        }
#pragma unroll
        for (int o = 16; o; o >>= 1) mx = fmaxf(mx, __shfl_xor_sync(0xffffffffu, mx, o));
        float sum = 0.f;
        for (int t = 0; t < jcnt; t++) { float e = expf(sv[t] - mx); sv[t] = e; sum += e; }
#pragma unroll
        for (int o = 16; o; o >>= 1) sum += __shfl_xor_sync(0xffffffffu, sum, o);
        float inv = 1.f / sum;
        for (int t = 0; t < jcnt; t++) ps[warp * Nl + t * 32 + lane] = sv[t] * inv;
        __syncwarp();

#pragma unroll
        for (int dd = 0; dd < 2; dd++) {
            int d = dd * 32 + lane;
            float acc = 0.f;
            for (int j = 0; j < Nl; j++) acc += ps[warp * Nl + j] * Vs[j * 65 + d];
            out[((size_t)b * Nl + r) * DIM + h * 64 + d] = acc;
        }
        __syncwarp();
    }
}

// ---------------------------------------------------------------------------
// Pairwise pooling: out[b,n,d] = 0.5*(p[b,2n,d] + p[b,2n+1,d]); n elements total
// ---------------------------------------------------------------------------
__global__ void pool_k(const float* __restrict__ p, float* __restrict__ o, int n)
{
    int i = blockIdx.x * blockDim.x + threadIdx.x;
    if (i >= n) return;
    int row = i >> 9, d = i & 511;
    size_t base = (size_t)row * 1024 + d;
    o[i] = 0.5f * (p[base] + p[base + 512]);
}

// ---------------------------------------------------------------------------
// Upsample + concat: cat[b,n, l*512+d] = lvl_l[b, n>>l, d]
// ---------------------------------------------------------------------------
__global__ void concat_k(const float* __restrict__ l0, const float* __restrict__ l1,
                         const float* __restrict__ l2, float* __restrict__ cat)
{
    int idx = blockIdx.x * blockDim.x + threadIdx.x;
    const int total = BB * NNODE * 3 * DIM;
    if (idx >= total) return;
    int c = idx % (3 * DIM);
    int n = (idx / (3 * DIM)) % NNODE;
    int b = idx / (3 * DIM * NNODE);
    int l = c >> 9, d = c & 511;
    const float* src = (l == 0) ? l0 : (l == 1) ? l1 : l2;
    int Nl = NNODE >> l;
    cat[idx] = src[((size_t)b * Nl + (n >> l)) * DIM + d];
}

// ---------------------------------------------------------------------------
// LayerNorm over last dim (512). One block of 128 threads per row, float4/thread.
// Two-pass variance to match reference mean/var computation.
// ---------------------------------------------------------------------------
__global__ void ln_k(const float* __restrict__ in, const float* __restrict__ g,
                     const float* __restrict__ bta, float* __restrict__ out)
{
    const int row = blockIdx.x, t = threadIdx.x;
    const int warp = t >> 5, lane = t & 31;
    float4 v = ((const float4*)(in + (size_t)row * DIM))[t];
    __shared__ float red[4];

    float s = v.x + v.y + v.z + v.w;
#pragma unroll
    for (int o = 16; o; o >>= 1) s += __shfl_xor_sync(0xffffffffu, s, o);
    if (lane == 0) red[warp] = s;
    __syncthreads();
    float mean = (red[0] + red[1] + red[2] + red[3]) * (1.f / DIM);
    __syncthreads();

    float dx = v.x - mean, dy = v.y - mean, dz = v.z - mean, dw = v.w - mean;
    float s2 = dx * dx + dy * dy + dz * dz + dw * dw;
#pragma unroll
    for (int o = 16; o; o >>= 1) s2 += __shfl_xor_sync(0xffffffffu, s2, o);
    if (lane == 0) red[warp] = s2;
    __syncthreads();
    float var = (red[0] + red[1] + red[2] + red[3]) * (1.f / DIM);
    float inv = 1.f / sqrtf(var + 1e-5f);

    float4 gv = ((const float4*)g)[t];
    float4 bv = ((const float4*)bta)[t];
    float4 r;
    r.x = dx * inv * gv.x + bv.x;
    r.y = dy * inv * gv.y + bv.y;
    r.z = dz * inv * gv.z + bv.z;
    r.w = dw * inv * gv.w + bv.w;
    ((float4*)(out + (size_t)row * DIM))[t] = r;
}

// ---------------------------------------------------------------------------
// Edge scores: sc[b,i,j] = sum_d relu(hi[b,i,d] + hj[b,j,d]) * w2[d]; diag -> -1e30
// (sigmoid and be2 are monotone/constant => dropped, ordering preserved for top-k)
// grid (4 jt, 4 it, B), block 256 (16x16), 64x64 tile, d in chunks of 16.
// ---------------------------------------------------------------------------
__global__ void scores_k(const float* __restrict__ hi, const float* __restrict__ hj,
                         const float* __restrict__ w2, float* __restrict__ sc)
{
    __shared__ float His[16][68];
    __shared__ float Hjs[16][68];
    __shared__ float W2s[16];
    const int b = blockIdx.z;
    const int i0 = blockIdx.y * 64, j0 = blockIdx.x * 64;
    const int tid = threadIdx.x;
    const int tx = tid & 15, ty = tid >> 4;
    const float* hib = hi + ((size_t)b * NNODE + i0) * DIM;
    const float* hjb = hj + ((size_t)b * NNODE + j0) * DIM;

    float acc[4][4];
#pragma unroll
    for (int i = 0; i < 4; i++)
#pragma unroll
        for (int j = 0; j < 4; j++) acc[i][j] = 0.f;

    const int irow = tid >> 2, kv = tid & 3;
    for (int k0 = 0; k0 < DIM; k0 += 16) {
        float4 a = *(const float4*)&hib[(size_t)irow * DIM + k0 + kv * 4];
        float4 c = *(const float4*)&hjb[(size_t)irow * DIM + k0 + kv * 4];
        His[kv * 4 + 0][irow] = a.x; His[kv * 4 + 1][irow] = a.y;
        His[kv * 4 + 2][irow] = a.z; His[kv * 4 + 3][irow] = a.w;
        Hjs[kv * 4 + 0][irow] = c.x; Hjs[kv * 4 + 1][irow] = c.y;
        Hjs[kv * 4 + 2][irow] = c.z; Hjs[kv * 4 + 3][irow] = c.w;
        if (tid < 16) W2s[tid] = w2[k0 + tid];
        __syncthreads();
#pragma unroll
        for (int kk = 0; kk < 16; kk++) {
            float4 h4 = *(const float4*)&His[kk][ty * 4];
            float4 j4 = *(const float4*)&Hjs[kk][tx * 4];
            float w = W2s[kk];
            float hv[4] = {h4.x, h4.y, h4.z, h4.w};
            float jv[4] = {j4.x, j4.y, j4.z, j4.w};
#pragma unroll
            for (int i = 0; i < 4; i++)
#pragma unroll
                for (int j = 0; j < 4; j++)
                    acc[i][j] += fmaxf(hv[i] + jv[j], 0.f) * w;
        }
        __syncthreads();
    }

#pragma unroll
    for (int i = 0; i < 4; i++) {
        int gi = i0 + ty * 4 + i;
#pragma unroll
        for (int j = 0; j < 4; j++) {
            int gj = j0 + tx * 4 + j;
            sc[((size_t)b * NNODE + gi) * NNODE + gj] = (gi == gj) ? -1e30f : acc[i][j];
        }
    }
}

// ---------------------------------------------------------------------------
// Top-k (k=25) per row of 256, warp per row. Tie-break: lower index (jax top_k).
// adj must be pre-zeroed; winners get 1.0f.
// ---------------------------------------------------------------------------
__global__ void topk_k(const float* __restrict__ sc, float* __restrict__ adj)
{
    const int warp = threadIdx.x >> 5, lane = threadIdx.x & 31;
    const int row = blockIdx.x * 8 + warp;   // 0 .. B*N-1
    const float* s = sc + (size_t)row * NNODE;
    float v[8];
#pragma unroll
    for (int t = 0; t < 8; t++) v[t] = s[t * 32 + lane];
    float* arow = adj + (size_t)row * NNODE;

    for (int it = 0; it < KSP; it++) {
        float bv = -3e38f; int bi = 0;
#pragma unroll
        for (int t = 0; t < 8; t++) {
            int j = t * 32 + lane;
            if (v[t] > bv) { bv = v[t]; bi = j; }   // strict > keeps lower index on ties
        }
#pragma unroll
        for (int o = 16; o; o >>= 1) {
            float ov = __shfl_xor_sync(0xffffffffu, bv, o);
            int   oi = __shfl_xor_sync(0xffffffffu, bi, o);
            if (ov > bv || (ov == bv && oi < bi)) { bv = ov; bi = oi; }
        }
        if (lane == (bi & 31)) v[bi >> 5] = -3e38f;
        if (lane == 0) arow[bi] = 1.0f;
        __syncwarp();
    }
}

__global__ void zero_k(float* __restrict__ p, int n)
{
    int i = blockIdx.x * blockDim.x + threadIdx.x;
    if (i < n) p[i] = 0.f;
}

// ---------------------------------------------------------------------------
// Host orchestration
// ---------------------------------------------------------------------------
static float* symaddr(const void* s)
{
    void* p = nullptr;
    cudaGetSymbolAddress(&p, s);
    return (float*)p;
}

extern "C" void kernel_launch(void* const* d_in, const int* in_sizes, int n_in,
                              void* d_out, int out_size)
{
    const float* x      = (const float*)d_in[0];
    // d_in[1] = adjacency (unused by reference)
    const float* Wqkv   = (const float*)d_in[2];
    const float* bqkv   = (const float*)d_in[3];
    const float* Wo     = (const float*)d_in[4];
    const float* bo     = (const float*)d_in[5];
    const float* Wp1    = (const float*)d_in[6];
    const float* bp1    = (const float*)d_in[7];
    const float* Wp2    = (const float*)d_in[8];
    const float* bp2    = (const float*)d_in[9];
    const float* Wfuse  = (const float*)d_in[10];
    const float* bfuse  = (const float*)d_in[11];
    const float* ln_g   = (const float*)d_in[12];
    const float* ln_b   = (const float*)d_in[13];
    const float* We1    = (const float*)d_in[14];
    const float* be1    = (const float*)d_in[15];
    const float* We2    = (const float*)d_in[16];
    // d_in[17] = be2 (constant shift: drops out of top-k ordering)
    const float* Ws_qkv = (const float*)d_in[18];
    const float* bs_qkv = (const float*)d_in[19];
    const float* Ws_o   = (const float*)d_in[20];
    const float* bs_o   = (const float*)d_in[21];

    float* out_att = (float*)d_out;                    // [B,N,D]
    float* out_adj = out_att + (size_t)BB * NNODE * DIM; // [B,N,N]

    float* cur  = symaddr(g_cur);
    float* qkv  = symaddr(g_qkv);
    float* atto = symaddr(g_atto);
    float* lvl0 = symaddr(g_lvl0);
    float* lvl1 = symaddr(g_lvl1);
    float* lvl2 = symaddr(g_lvl2);
    float* t1   = symaddr(g_t1);
    float* pbuf = symaddr(g_p);
    float* cat  = symaddr(g_cat);
    float* hier = symaddr(g_hier);
    float* hi   = symaddr(g_hi);
    float* hj   = symaddr(g_hj);
    float* sc   = symaddr(g_sc);

    // opt-in to large dynamic shared memory for attention (143360 B at Nl=256)
    cudaFuncSetAttribute(attn_k, cudaFuncAttributeMaxDynamicSharedMemorySize, 150000);

    float* lvls[3] = {lvl0, lvl1, lvl2};
    const float* curp = x;

    for (int l = 0; l < 3; l++) {
        const int Nl = NNODE >> l;
        const int M  = BB * Nl;
        // qkv = cur @ Wqkv[l] + bqkv[l]
        sgemm_k<<<dim3(3 * DIM / 64, M / 64), 256>>>(
            curp, Wqkv + (size_t)l * DIM * 3 * DIM, bqkv + (size_t)l * 3 * DIM,
            qkv, M, DIM, 3 * DIM, 0);
        // attention
        size_t smem = (size_t)(Nl * 65 * 2 + 8 * 64 + 8 * Nl) * sizeof(float);
        attn_k<<<dim3(BB * NH, 4), 256, smem>>>(qkv, atto, Nl);
        // out proj -> level output
        sgemm_k<<<dim3(DIM / 64, M / 64), 256>>>(
            atto, Wo + (size_t)l * DIM * DIM, bo + (size_t)l * DIM,
            lvls[l], M, DIM, DIM, 0);
        if (l < 2) {
            sgemm_k<<<dim3(DIM / 2 / 64, M / 64), 256>>>(
                lvls[l], Wp1 + (size_t)l * DIM * (DIM / 2), bp1 + (size_t)l * (DIM / 2),
                t1, M, DIM, DIM / 2, 1);
            sgemm_k<<<dim3(DIM / 64, M / 64), 256>>>(
                t1, Wp2 + (size_t)l * (DIM / 2) * DIM, bp2 + (size_t)l * DIM,
                pbuf, M, DIM / 2, DIM, 0);
            int n = BB * (Nl / 2) * DIM;
            pool_k<<<(n + 255) / 256, 256>>>(pbuf, cur, n);
            curp = cur;
        }
    }

    // fuse: concat upsampled levels -> GEMM(relu) -> LayerNorm
    {
        const int total = BB * NNODE * 3 * DIM;
        concat_k<<<(total + 255) / 256, 256>>>(lvl0, lvl1, lvl2, cat);
        sgemm_k<<<dim3(DIM / 64, BB * NNODE / 64), 256>>>(
            cat, Wfuse, bfuse, pbuf, BB * NNODE, 3 * DIM, DIM, 1);
        ln_k<<<BB * NNODE, 128>>>(pbuf, ln_g, ln_b, hier);
    }

    // sparse edge scoring + top-k
    {
        sgemm_k<<<dim3(DIM / 64, BB * NNODE / 64), 256>>>(
            hier, We1, nullptr, hi, BB * NNODE, DIM, DIM, 0);
        sgemm_k<<<dim3(DIM / 64, BB * NNODE / 64), 256>>>(
            hier, We1 + (size_t)DIM * DIM, be1, hj, BB * NNODE, DIM, DIM, 0);
        scores_k<<<dim3(NNODE / 64, NNODE / 64, BB), 256>>>(hi, hj, We2, sc);
        int n = BB * NNODE * NNODE;
        zero_k<<<(n + 255) / 256, 256>>>(out_adj, n);
        topk_k<<<BB * NNODE / 8, 256>>>(sc, out_adj);
    }

    // final sparse-attention MHA on hier -> attended output
    {
        const int M = BB * NNODE;
        sgemm_k<<<dim3(3 * DIM / 64, M / 64), 256>>>(
            hier, Ws_qkv, bs_qkv, qkv, M, DIM, 3 * DIM, 0);
        size_t smem = (size_t)(NNODE * 65 * 2 + 8 * 64 + 8 * NNODE) * sizeof(float);
        attn_k<<<dim3(BB * NH, 4), 256, smem>>>(qkv, atto, NNODE);
        sgemm_k<<<dim3(DIM / 64, M / 64), 256>>>(
            atto, Ws_o, bs_o, out_att, M, DIM, DIM, 0);
    }
}

// round 2
// speedup vs baseline: 1.1489x; 1.1489x over previous
#include <cuda_runtime.h>
#include <math.h>

#define BB 4
#define NNODE 256
#define DIM 512
#define NH 8
#define KSP 25

// ---------------------------------------------------------------------------
// Scratch (no allocations allowed anywhere)
// ---------------------------------------------------------------------------
__device__ float g_cur [BB*NNODE*DIM];
__device__ float g_qkv [BB*NNODE*3*DIM];
__device__ float g_atto[BB*NNODE*DIM];
__device__ float g_lvl0[BB*NNODE*DIM];
__device__ float g_lvl1[BB*(NNODE/2)*DIM];
__device__ float g_lvl2[BB*(NNODE/4)*DIM];
__device__ float g_t1  [BB*NNODE*(DIM/2)];
__device__ float g_p   [BB*NNODE*DIM];
__device__ float g_cat [BB*NNODE*3*DIM];
__device__ float g_hier[BB*NNODE*DIM];
__device__ float g_hi  [BB*NNODE*DIM];
__device__ float g_hj  [BB*NNODE*DIM];
__device__ float g_sc  [BB*NNODE*NNODE];

// packed fp32x2 helpers (bit-exact dual fp32; FFMA2 only reachable via PTX)
__device__ __forceinline__ unsigned long long pack2(float lo, float hi) {
    unsigned long long r;
    asm("mov.b64 %0, {%1, %2};" : "=l"(r) : "f"(lo), "f"(hi));
    return r;
}
__device__ __forceinline__ void unpack2(unsigned long long v, float& lo, float& hi) {
    asm("mov.b64 {%0, %1}, %2;" : "=f"(lo), "=f"(hi) : "l"(v));
}
__device__ __forceinline__ void ffma2(unsigned long long& d,
                                      unsigned long long a, unsigned long long b) {
    asm("fma.rn.f32x2 %0, %1, %2, %0;" : "+l"(d) : "l"(a), "l"(b));
}

// ---------------------------------------------------------------------------
// SGEMM: C[M,Nc] = A[M,K] @ W[K,Nc] (+bias) (+relu)
// M multiple of 128, Nc multiple of 64, K multiple of 16.
// 256 threads, 128x64 tile, 8x4 per thread, double-buffered smem,
// packed f32x2 FMA core.
// ---------------------------------------------------------------------------
__global__ void __launch_bounds__(256, 2)
sgemm_k(const float* __restrict__ A, const float* __restrict__ W,
        const float* __restrict__ bias, float* __restrict__ C,
        int M, int K, int Nc, int relu)
{
    __shared__ float As[2][16][128];
    __shared__ float Bs[2][16][64];

    const int bm = blockIdx.y * 128, bn = blockIdx.x * 64;
    const int tid = threadIdx.x;
    const int tx = tid & 15;        // n: 4 outputs
    const int ty = tid >> 4;        // m: 8 outputs

    unsigned long long acc[8][2];
#pragma unroll
    for (int i = 0; i < 8; i++) { acc[i][0] = 0ull; acc[i][1] = 0ull; }

    const int nk = K >> 4;

    // A-load mapping: f = tid*2+i -> row f>>2, colv f&3
    const int ar = (tid * 2) >> 2;      // row for i=0 (i=1 may differ)
    float4 areg[2];
    float4 breg;
    const int bkw = tid >> 4, bnv = tid & 15;

    // prefetch chunk 0
#pragma unroll
    for (int i = 0; i < 2; i++) {
        int f = tid * 2 + i, r = f >> 2, c = f & 3;
        areg[i] = *(const float4*)&A[(size_t)(bm + r) * K + c * 4];
    }
    breg = *(const float4*)&W[(size_t)bkw * Nc + bn + bnv * 4];
    // store stage 0
#pragma unroll
    for (int i = 0; i < 2; i++) {
        int f = tid * 2 + i, r = f >> 2, c = f & 3;
        As[0][c * 4 + 0][r] = areg[i].x;
        As[0][c * 4 + 1][r] = areg[i].y;
        As[0][c * 4 + 2][r] = areg[i].z;
        As[0][c * 4 + 3][r] = areg[i].w;
    }
    *(float4*)&Bs[0][bkw][bnv * 4] = breg;
    __syncthreads();

    for (int k0 = 0; k0 < nk; k0++) {
        const int buf = k0 & 1;
        if (k0 + 1 < nk) {
            const int kb = (k0 + 1) << 4;
#pragma unroll
            for (int i = 0; i < 2; i++) {
                int f = tid * 2 + i, r = f >> 2, c = f & 3;
                areg[i] = *(const float4*)&A[(size_t)(bm + r) * K + kb + c * 4];
            }
            breg = *(const float4*)&W[(size_t)(kb + bkw) * Nc + bn + bnv * 4];
        }
#pragma unroll
        for (int kk = 0; kk < 16; kk++) {
            float4 a0 = *(const float4*)&As[buf][kk][ty * 8];
            float4 a1 = *(const float4*)&As[buf][kk][ty * 8 + 4];
            float4 b  = *(const float4*)&Bs[buf][kk][tx * 4];
            unsigned long long b01 = pack2(b.x, b.y);
            unsigned long long b23 = pack2(b.z, b.w);
            float av[8] = {a0.x, a0.y, a0.z, a0.w, a1.x, a1.y, a1.z, a1.w};
#pragma unroll
            for (int i = 0; i < 8; i++) {
                unsigned long long aa = pack2(av[i], av[i]);
                ffma2(acc[i][0], aa, b01);
                ffma2(acc[i][1], aa, b23);
            }
        }
        if (k0 + 1 < nk) {
            const int nb = buf ^ 1;
#pragma unroll
            for (int i = 0; i < 2; i++) {
                int f = tid * 2 + i, r = f >> 2, c = f & 3;
                As[nb][c * 4 + 0][r] = areg[i].x;
                As[nb][c * 4 + 1][r] = areg[i].y;
                As[nb][c * 4 + 2][r] = areg[i].z;
                As[nb][c * 4 + 3][r] = areg[i].w;
            }
            *(float4*)&Bs[nb][bkw][bnv * 4] = breg;
        }
        __syncthreads();
    }

    float4 bb = make_float4(0.f, 0.f, 0.f, 0.f);
    if (bias) bb = *(const float4*)&bias[bn + tx * 4];
#pragma unroll
    for (int i = 0; i < 8; i++) {
        int m = bm + ty * 8 + i;
        float4 r;
        unpack2(acc[i][0], r.x, r.y);
        unpack2(acc[i][1], r.z, r.w);
        r.x += bb.x; r.y += bb.y; r.z += bb.z; r.w += bb.w;
        if (relu) {
            r.x = fmaxf(r.x, 0.f); r.y = fmaxf(r.y, 0.f);
            r.z = fmaxf(r.z, 0.f); r.w = fmaxf(r.w, 0.f);
        }
        *(float4*)&C[(size_t)m * Nc + bn + tx * 4] = r;
    }
    (void)ar;
}

// ---------------------------------------------------------------------------
// Multi-head attention core: qkv [B, Nl, 3*DIM] -> out [B, Nl, DIM]
// grid (B*NH, 4), block 256. K/V resident in shared, pitch 68 floats
// (conflict-free float4 LDS).
// ---------------------------------------------------------------------------
__global__ void attn_k(const float* __restrict__ qkv, float* __restrict__ out, int Nl)
{
    extern __shared__ float sm[];
    float* Ks = sm;                  // Nl*68
    float* Vs = Ks + Nl * 68;        // Nl*68
    float* qs = Vs + Nl * 68;        // 8*64
    float* ps = qs + 8 * 64;         // 8*Nl

    const int b = blockIdx.x >> 3, h = blockIdx.x & 7;
    const float* base = qkv + (size_t)b * Nl * (3 * DIM);
    const int tid = threadIdx.x, warp = tid >> 5, lane = tid & 31;

    for (int idx = tid; idx < Nl * 16; idx += 256) {
        int n = idx >> 4, dv = idx & 15;
        const float* rowp = base + (size_t)n * (3 * DIM) + h * 64 + dv * 4;
        *(float4*)&Ks[n * 68 + dv * 4] = *(const float4*)(rowp + DIM);
        *(float4*)&Vs[n * 68 + dv * 4] = *(const float4*)(rowp + 2 * DIM);
    }
    __syncthreads();

    const int jcnt = Nl >> 5;   // <= 8
    for (int r = blockIdx.y * 8 + warp; r < Nl; r += 8 * gridDim.y) {
        if (lane < 16)
            ((float4*)&qs[warp * 64])[lane] =
                *(const float4*)&base[(size_t)r * (3 * DIM) + h * 64 + lane * 4];
        __syncwarp();

        const float4* qr = (const float4*)&qs[warp * 64];
        float sv[8];
        float mx = -1e30f;
        for (int t = 0; t < jcnt; t++) {
            int j = t * 32 + lane;
            const float4* kr = (const float4*)&Ks[j * 68];
            float s = 0.f;
#pragma unroll
            for (int d4 = 0; d4 < 16; d4++) {
                float4 q4 = qr[d4], k4 = kr[d4];
                s += q4.x * k4.x + q4.y * k4.y + q4.z * k4.z + q4.w * k4.w;
            }
            s *= 0.125f;           // HD^-0.5
            sv[t] = s;
            mx = fmaxf(mx, s);
        }
#pragma unroll
        for (int o = 16; o; o >>= 1) mx = fmaxf(mx, __shfl_xor_sync(0xffffffffu, mx, o));
        float sum = 0.f;
        for (int t = 0; t < jcnt; t++) { float e = expf(sv[t] - mx); sv[t] = e; sum += e; }
#pragma unroll
        for (int o = 16; o; o >>= 1) sum += __shfl_xor_sync(0xffffffffu, sum, o);
        float inv = 1.f / sum;
        for (int t = 0; t < jcnt; t++) ps[warp * Nl + t * 32 + lane] = sv[t] * inv;
        __syncwarp();

#pragma unroll
        for (int dd = 0; dd < 2; dd++) {
            int d = dd * 32 + lane;
            float acc = 0.f;
            for (int j = 0; j < Nl; j += 4) {
                acc += ps[warp * Nl + j]     * Vs[(j)     * 68 + d];
                acc += ps[warp * Nl + j + 1] * Vs[(j + 1) * 68 + d];
                acc += ps[warp * Nl + j + 2] * Vs[(j + 2) * 68 + d];
                acc += ps[warp * Nl + j + 3] * Vs[(j + 3) * 68 + d];
            }
            out[((size_t)b * Nl + r) * DIM + h * 64 + d] = acc;
        }
        __syncwarp();
    }
}

// ---------------------------------------------------------------------------
// Pairwise pooling
// ---------------------------------------------------------------------------
__global__ void pool_k(const float* __restrict__ p, float* __restrict__ o, int n)
{
    int i = blockIdx.x * blockDim.x + threadIdx.x;
    if (i >= n) return;
    int row = i >> 9, d = i & 511;
    size_t base = (size_t)row * 1024 + d;
    o[i] = 0.5f * (p[base] + p[base + 512]);
}

// ---------------------------------------------------------------------------
// Upsample + concat
// ---------------------------------------------------------------------------
__global__ void concat_k(const float* __restrict__ l0, const float* __restrict__ l1,
                         const float* __restrict__ l2, float* __restrict__ cat)
{
    int idx = blockIdx.x * blockDim.x + threadIdx.x;
    const int total = BB * NNODE * 3 * DIM;
    if (idx >= total) return;
    int c = idx % (3 * DIM);
    int n = (idx / (3 * DIM)) % NNODE;
    int b = idx / (3 * DIM * NNODE);
    int l = c >> 9, d = c & 511;
    const float* src = (l == 0) ? l0 : (l == 1) ? l1 : l2;
    int Nl = NNODE >> l;
    cat[idx] = src[((size_t)b * Nl + (n >> l)) * DIM + d];
}

// ---------------------------------------------------------------------------
// LayerNorm over last dim (512)
// ---------------------------------------------------------------------------
__global__ void ln_k(const float* __restrict__ in, const float* __restrict__ g,
                     const float* __restrict__ bta, float* __restrict__ out)
{
    const int row = blockIdx.x, t = threadIdx.x;
    const int warp = t >> 5, lane = t & 31;
    float4 v = ((const float4*)(in + (size_t)row * DIM))[t];
    __shared__ float red[4];

    float s = v.x + v.y + v.z + v.w;
#pragma unroll
    for (int o = 16; o; o >>= 1) s += __shfl_xor_sync(0xffffffffu, s, o);
    if (lane == 0) red[warp] = s;
    __syncthreads();
    float mean = (red[0] + red[1] + red[2] + red[3]) * (1.f / DIM);
    __syncthreads();

    float dx = v.x - mean, dy = v.y - mean, dz = v.z - mean, dw = v.w - mean;
    float s2 = dx * dx + dy * dy + dz * dz + dw * dw;
#pragma unroll
    for (int o = 16; o; o >>= 1) s2 += __shfl_xor_sync(0xffffffffu, s2, o);
    if (lane == 0) red[warp] = s2;
    __syncthreads();
    float var = (red[0] + red[1] + red[2] + red[3]) * (1.f / DIM);
    float inv = 1.f / sqrtf(var + 1e-5f);

    float4 gv = ((const float4*)g)[t];
    float4 bv = ((const float4*)bta)[t];
    float4 r;
    r.x = dx * inv * gv.x + bv.x;
    r.y = dy * inv * gv.y + bv.y;
    r.z = dz * inv * gv.z + bv.z;
    r.w = dw * inv * gv.w + bv.w;
    ((float4*)(out + (size_t)row * DIM))[t] = r;
}

// ---------------------------------------------------------------------------
// Edge scores: sc[b,i,j] = sum_d relu(hi[b,i,d] + hj[b,j,d]) * w2[d]; diag -> -1e30
// ---------------------------------------------------------------------------
__global__ void scores_k(const float* __restrict__ hi, const float* __restrict__ hj,
                         const float* __restrict__ w2, float* __restrict__ sc)
{
    __shared__ float His[16][68];
    __shared__ float Hjs[16][68];
    __shared__ float W2s[16];
    const int b = blockIdx.z;
    const int i0 = blockIdx.y * 64, j0 = blockIdx.x * 64;
    const int tid = threadIdx.x;
    const int tx = tid & 15, ty = tid >> 4;
    const float* hib = hi + ((size_t)b * NNODE + i0) * DIM;
    const float* hjb = hj + ((size_t)b * NNODE + j0) * DIM;

    float acc[4][4];
#pragma unroll
    for (int i = 0; i < 4; i++)
#pragma unroll
        for (int j = 0; j < 4; j++) acc[i][j] = 0.f;

    const int irow = tid >> 2, kv = tid & 3;
    for (int k0 = 0; k0 < DIM; k0 += 16) {
        float4 a = *(const float4*)&hib[(size_t)irow * DIM + k0 + kv * 4];
        float4 c = *(const float4*)&hjb[(size_t)irow * DIM + k0 + kv * 4];
        His[kv * 4 + 0][irow] = a.x; His[kv * 4 + 1][irow] = a.y;
        His[kv * 4 + 2][irow] = a.z; His[kv * 4 + 3][irow] = a.w;
        Hjs[kv * 4 + 0][irow] = c.x; Hjs[kv * 4 + 1][irow] = c.y;
        Hjs[kv * 4 + 2][irow] = c.z; Hjs[kv * 4 + 3][irow] = c.w;
        if (tid < 16) W2s[tid] = w2[k0 + tid];
        __syncthreads();
#pragma unroll
        for (int kk = 0; kk < 16; kk++) {
            float4 h4 = *(const float4*)&His[kk][ty * 4];
            float4 j4 = *(const float4*)&Hjs[kk][tx * 4];
            float w = W2s[kk];
            float hv[4] = {h4.x, h4.y, h4.z, h4.w};
            float jv[4] = {j4.x, j4.y, j4.z, j4.w};
#pragma unroll
            for (int i = 0; i < 4; i++)
#pragma unroll
                for (int j = 0; j < 4; j++)
                    acc[i][j] += fmaxf(hv[i] + jv[j], 0.f) * w;
        }
        __syncthreads();
    }

#pragma unroll
    for (int i = 0; i < 4; i++) {
        int gi = i0 + ty * 4 + i;
#pragma unroll
        for (int j = 0; j < 4; j++) {
            int gj = j0 + tx * 4 + j;
            sc[((size_t)b * NNODE + gi) * NNODE + gj] = (gi == gj) ? -1e30f : acc[i][j];
        }
    }
}

// ---------------------------------------------------------------------------
// Top-k (k=25) per row, warp per row; also zeroes its row first.
// ---------------------------------------------------------------------------
__global__ void topk_k(const float* __restrict__ sc, float* __restrict__ adj)
{
    const int warp = threadIdx.x >> 5, lane = threadIdx.x & 31;
    const int row = blockIdx.x * 8 + warp;
    const float* s = sc + (size_t)row * NNODE;
    float v[8];
#pragma unroll
    for (int t = 0; t < 8; t++) v[t] = s[t * 32 + lane];
    float* arow = adj + (size_t)row * NNODE;
#pragma unroll
    for (int t = 0; t < 8; t++) arow[t * 32 + lane] = 0.f;
    __syncwarp();

    for (int it = 0; it < KSP; it++) {
        float bv = -3e38f; int bi = 0;
#pragma unroll
        for (int t = 0; t < 8; t++) {
            int j = t * 32 + lane;
            if (v[t] > bv) { bv = v[t]; bi = j; }
        }
#pragma unroll
        for (int o = 16; o; o >>= 1) {
            float ov = __shfl_xor_sync(0xffffffffu, bv, o);
            int   oi = __shfl_xor_sync(0xffffffffu, bi, o);
            if (ov > bv || (ov == bv && oi < bi)) { bv = ov; bi = oi; }
        }
        if (lane == (bi & 31)) v[bi >> 5] = -3e38f;
        if (lane == 0) arow[bi] = 1.0f;
        __syncwarp();
    }
}

// ---------------------------------------------------------------------------
// Host orchestration
// ---------------------------------------------------------------------------
static float* symaddr(const void* s)
{
    void* p = nullptr;
    cudaGetSymbolAddress(&p, s);
    return (float*)p;
}

extern "C" void kernel_launch(void* const* d_in, const int* in_sizes, int n_in,
                              void* d_out, int out_size)
{
    const float* x      = (const float*)d_in[0];
    const float* Wqkv   = (const float*)d_in[2];
    const float* bqkv   = (const float*)d_in[3];
    const float* Wo     = (const float*)d_in[4];
    const float* bo     = (const float*)d_in[5];
    const float* Wp1    = (const float*)d_in[6];
    const float* bp1    = (const float*)d_in[7];
    const float* Wp2    = (const float*)d_in[8];
    const float* bp2    = (const float*)d_in[9];
    const float* Wfuse  = (const float*)d_in[10];
    const float* bfuse  = (const float*)d_in[11];
    const float* ln_g   = (const float*)d_in[12];
    const float* ln_b   = (const float*)d_in[13];
    const float* We1    = (const float*)d_in[14];
    const float* be1    = (const float*)d_in[15];
    const float* We2    = (const float*)d_in[16];
    const float* Ws_qkv = (const float*)d_in[18];
    const float* bs_qkv = (const float*)d_in[19];
    const float* Ws_o   = (const float*)d_in[20];
    const float* bs_o   = (const float*)d_in[21];

    float* out_att = (float*)d_out;                      // [B,N,D]
    float* out_adj = out_att + (size_t)BB * NNODE * DIM; // [B,N,N]

    float* cur  = symaddr(g_cur);
    float* qkv  = symaddr(g_qkv);
    float* atto = symaddr(g_atto);
    float* lvl0 = symaddr(g_lvl0);
    float* lvl1 = symaddr(g_lvl1);
    float* lvl2 = symaddr(g_lvl2);
    float* t1   = symaddr(g_t1);
    float* pbuf = symaddr(g_p);
    float* cat  = symaddr(g_cat);
    float* hier = symaddr(g_hier);
    float* hi   = symaddr(g_hi);
    float* hj   = symaddr(g_hj);
    float* sc   = symaddr(g_sc);

    cudaFuncSetAttribute(attn_k, cudaFuncAttributeMaxDynamicSharedMemorySize, 160000);

    float* lvls[3] = {lvl0, lvl1, lvl2};
    const float* curp = x;

    for (int l = 0; l < 3; l++) {
        const int Nl = NNODE >> l;
        const int M  = BB * Nl;
        sgemm_k<<<dim3(3 * DIM / 64, M / 128), 256>>>(
            curp, Wqkv + (size_t)l * DIM * 3 * DIM, bqkv + (size_t)l * 3 * DIM,
            qkv, M, DIM, 3 * DIM, 0);
        size_t smem = (size_t)(Nl * 68 * 2 + 8 * 64 + 8 * Nl) * sizeof(float);
        attn_k<<<dim3(BB * NH, 4), 256, smem>>>(qkv, atto, Nl);
        sgemm_k<<<dim3(DIM / 64, M / 128), 256>>>(
            atto, Wo + (size_t)l * DIM * DIM, bo + (size_t)l * DIM,
            lvls[l], M, DIM, DIM, 0);
        if (l < 2) {
            sgemm_k<<<dim3(DIM / 2 / 64, M / 128), 256>>>(
                lvls[l], Wp1 + (size_t)l * DIM * (DIM / 2), bp1 + (size_t)l * (DIM / 2),
                t1, M, DIM, DIM / 2, 1);
            sgemm_k<<<dim3(DIM / 64, M / 128), 256>>>(
                t1, Wp2 + (size_t)l * (DIM / 2) * DIM, bp2 + (size_t)l * DIM,
                pbuf, M, DIM / 2, DIM, 0);
            int n = BB * (Nl / 2) * DIM;
            pool_k<<<(n + 255) / 256, 256>>>(pbuf, cur, n);
            curp = cur;
        }
    }

    // fuse: concat upsampled levels -> GEMM(relu) -> LayerNorm
    {
        const int total = BB * NNODE * 3 * DIM;
        concat_k<<<(total + 255) / 256, 256>>>(lvl0, lvl1, lvl2, cat);
        sgemm_k<<<dim3(DIM / 64, BB * NNODE / 128), 256>>>(
            cat, Wfuse, bfuse, pbuf, BB * NNODE, 3 * DIM, DIM, 1);
        ln_k<<<BB * NNODE, 128>>>(pbuf, ln_g, ln_b, hier);
    }

    // sparse edge scoring + top-k
    {
        sgemm_k<<<dim3(DIM / 64, BB * NNODE / 128), 256>>>(
            hier, We1, nullptr, hi, BB * NNODE, DIM, DIM, 0);
        sgemm_k<<<dim3(DIM / 64, BB * NNODE / 128), 256>>>(
            hier, We1 + (size_t)DIM * DIM, be1, hj, BB * NNODE, DIM, DIM, 0);
        scores_k<<<dim3(NNODE / 64, NNODE / 64, BB), 256>>>(hi, hj, We2, sc);
        topk_k<<<BB * NNODE / 8, 256>>>(sc, out_adj);
    }

    // final MHA on hier -> attended output
    {
        const int M = BB * NNODE;
        sgemm_k<<<dim3(3 * DIM / 64, M / 128), 256>>>(
            hier, Ws_qkv, bs_qkv, qkv, M, DIM, 3 * DIM, 0);
        size_t smem = (size_t)(NNODE * 68 * 2 + 8 * 64 + 8 * NNODE) * sizeof(float);
        attn_k<<<dim3(BB * NH, 4), 256, smem>>>(qkv, atto, NNODE);
        sgemm_k<<<dim3(DIM / 64, M / 128), 256>>>(
            atto, Ws_o, bs_o, out_att, M, DIM, DIM, 0);
    }
}